// round 14
// baseline (speedup 1.0000x reference)
#include <cuda_runtime.h>
#include <cuda_bf16.h>

// Problem constants (fixed by the reference setup)
constexpr int N    = 100000;   // nodes
constexpr int E    = 300000;   // directed edges
constexpr int NG   = 4096;     // graphs
constexpr int HID  = 128;
constexpr int FIN  = 22;

constexpr int NBLK = (N + 255) / 256;    // 391 scan blocks
constexpr int BN_CHUNK  = 100;
constexpr int BN_BLOCKS = N / BN_CHUNK;  // 1000

// ---------------- scratch (device globals; no allocations allowed) ----------
__device__ float g_h[N * HID];        // transformed features h = A@W (per layer)
__device__ float g_out[N * HID];      // aggregated messages (per layer)
__device__ float g_als[N * 4];        // per-node src attention logits
__device__ float g_ald[N * 4];        // per-node dst attention logits
__device__ float g_bnsum[HID];
__device__ float g_bnsq[HID];
__device__ float g_bnpart[BN_BLOCKS * 2 * HID];
// CSR (built once per launch, reused by all 3 layers)
__device__ int g_deg[N];
__device__ int g_fill[N];
__device__ int g_bsum[NBLK];
__device__ int g_bbase[NBLK];
__device__ int g_rowp[N + 1];
__device__ int g_csrc[E];

// ======================= CSR construction (fully parallel scan) ==============
__global__ void csr_zero() {
    int i = blockIdx.x * 256 + threadIdx.x;
    if (i < N) { g_deg[i] = 0; g_fill[i] = 0; }
}

__global__ void csr_deg(const int* __restrict__ ei) {
    int e = blockIdx.x * 256 + threadIdx.x;
    if (e < E) atomicAdd(&g_deg[ei[E + e]], 1);
}

// Level 1: per-block sum of 256 degrees -> g_bsum
__global__ void csr_bsum() {
    __shared__ int sw[8];
    int b = blockIdx.x, t = threadIdx.x;
    int i = b * 256 + t;
    int v = (i < N) ? g_deg[i] : 0;
#pragma unroll
    for (int o = 16; o; o >>= 1) v += __shfl_down_sync(0xFFFFFFFFu, v, o);
    if ((t & 31) == 0) sw[t >> 5] = v;
    __syncthreads();
    if (t == 0) {
        int s = 0;
#pragma unroll
        for (int j = 0; j < 8; j++) s += sw[j];
        g_bsum[b] = s;
    }
}

// Level 2: single-block exclusive scan of NBLK block sums -> g_bbase
__global__ void csr_scan1() {
    __shared__ int ss[512];
    int t = threadIdx.x;
    int s0 = (t < NBLK) ? g_bsum[t] : 0;
    ss[t] = s0;
    __syncthreads();
    for (int o = 1; o < 512; o <<= 1) {
        int v = (t >= o) ? ss[t - o] : 0;
        __syncthreads();
        ss[t] += v;
        __syncthreads();
    }
    if (t < NBLK) g_bbase[t] = ss[t] - s0;
}

// Level 3: per-block inclusive scan (shfl) + base -> g_rowp
__global__ void csr_rowp2() {
    __shared__ int sw[8];
    int b = blockIdx.x, t = threadIdx.x;
    int lane = t & 31, w = t >> 5;
    int i = b * 256 + t;
    int d = (i < N) ? g_deg[i] : 0;
    int v = d;
#pragma unroll
    for (int o = 1; o < 32; o <<= 1) {
        int u = __shfl_up_sync(0xFFFFFFFFu, v, o);
        if (lane >= o) v += u;
    }
    if (lane == 31) sw[w] = v;
    __syncthreads();
    if (t == 0) {
        int r = 0;
#pragma unroll
        for (int j = 0; j < 8; j++) { int x = sw[j]; sw[j] = r; r += x; }
    }
    __syncthreads();
    int base = g_bbase[b] + sw[w];
    if (i < N)      g_rowp[i] = base + v - d;   // exclusive
    if (i == N - 1) g_rowp[N] = base + v;
}

__global__ void csr_fill(const int* __restrict__ ei) {
    int e = blockIdx.x * 256 + threadIdx.x;
    if (e >= E) return;
    int d = ei[E + e];
    int pos = g_rowp[d] + atomicAdd(&g_fill[d], 1);
    g_csrc[pos] = ei[e];
}

// ======================= GEMM + fused attention projections ==================
// h = A[N,K] @ W[K,128];  al_s[n,h] = sum_c h[n,h*C+c]*a_s[h,c]  (same a_d)
// 128 threads (one per output feature), NPB=16 nodes per block.
// f32x2 packed FMA; node pairs in 64-bit accumulators; k-major smem staging
// read with 16B vector loads. SRC: 0 = external pointer (layer-1 x);
// 1 = g_out with fused BN+ReLU (stats in g_bnsum/g_bnsq). Device symbols are
// referenced IN-KERNEL only (host-side symbol pass = ATS host shadow = zeros).
template<int K, int H, int SRC>
__global__ void gemm_att(const float* __restrict__ Aext, const float* __restrict__ W,
                         const float* __restrict__ a_s, const float* __restrict__ a_d,
                         const float* __restrict__ gma, const float* __restrict__ bta)
{
    constexpr int NPB = 16;
    __shared__ __align__(16) float sA[K][NPB];   // k-major: node pairs contiguous
    __shared__ float sredS[NPB][4];
    __shared__ float sredD[NPB][4];

    const int n0 = blockIdx.x * NPB;
    const int f  = threadIdx.x;

    // Stage NPB input rows (transposed), BN+ReLU fused when SRC==1.
    for (int i = f; i < NPB * K; i += 128) {
        int t = i / K, k = i - t * K;
        float v;
        if (SRC == 0) {
            v = Aext[(n0 + t) * K + k];
        } else {
            float raw = g_out[(n0 + t) * K + k];
            float m   = g_bnsum[k] * (1.0f / N);
            float var = g_bnsq[k] * (1.0f / N) - m * m;
            float y = (raw - m) * rsqrtf(var + 1e-5f) * gma[k] + bta[k];
            v = y > 0.f ? y : 0.f;
        }
        sA[k][t] = v;
    }
    __syncthreads();

    unsigned long long acc[NPB / 2];
#pragma unroll
    for (int p = 0; p < NPB / 2; p++) acc[p] = 0ull;

#pragma unroll 4
    for (int k = 0; k < K; k++) {
        float w = W[k * HID + f];
        unsigned long long ww;
        asm("mov.b64 %0, {%1, %1};" : "=l"(ww) : "r"(__float_as_uint(w)));
        const ulonglong2* ap = reinterpret_cast<const ulonglong2*>(&sA[k][0]);
#pragma unroll
        for (int q = 0; q < NPB / 4; q++) {
            ulonglong2 a2 = ap[q];                 // 16B vector load (4 nodes)
            asm("fma.rn.f32x2 %0, %1, %2, %0;" : "+l"(acc[2*q])   : "l"(a2.x), "l"(ww));
            asm("fma.rn.f32x2 %0, %1, %2, %0;" : "+l"(acc[2*q+1]) : "l"(a2.y), "l"(ww));
        }
    }

    // Unpack accumulators
    float a[NPB];
#pragma unroll
    for (int p = 0; p < NPB / 2; p++) {
        unsigned int lo, hi;
        asm("mov.b64 {%0, %1}, %2;" : "=r"(lo), "=r"(hi) : "l"(acc[p]));
        a[2 * p]     = __uint_as_float(lo);
        a[2 * p + 1] = __uint_as_float(hi);
    }

    const float as_f = a_s[f];
    const float ad_f = a_d[f];
    const int warp = f >> 5, lane = f & 31;

#pragma unroll
    for (int t = 0; t < NPB; t++) {
        g_h[(n0 + t) * HID + f] = a[t];
        float vs = a[t] * as_f;
        float vd = a[t] * ad_f;
#pragma unroll
        for (int o = 16; o; o >>= 1) {
            vs += __shfl_down_sync(0xFFFFFFFFu, vs, o);
            vd += __shfl_down_sync(0xFFFFFFFFu, vd, o);
        }
        if (lane == 0) { sredS[t][warp] = vs; sredD[t][warp] = vd; }
    }
    __syncthreads();

    if (H == 4) {
        if (f < 64) {
            int t = f >> 2, w = f & 3;
            g_als[(n0 + t) * 4 + w] = sredS[t][w];
            g_ald[(n0 + t) * 4 + w] = sredD[t][w];
        }
    } else { // H == 1
        if (f < NPB) {
            float s = 0.f, d = 0.f;
#pragma unroll
            for (int w = 0; w < 4; w++) { s += sredS[f][w]; d += sredD[f][w]; }
            g_als[n0 + f] = s;
            g_ald[n0 + f] = d;
        }
    }
}

// ======================= Fused attention softmax + aggregation ===============
// One warp per dst node: out[d] = (sum_e ex_e * h[src_e]) / (sum_e ex_e + 1e-16)
// with ex_e = exp(leaky_relu(als[src]+ald[d])). Segment_max skipped
// (shift-invariant; logits O(1)). No atomics, no zeroing, no per-edge buffers.
template<int H>
__global__ void node_aggr()
{
    const int warp = threadIdx.x >> 5, lane = threadIdx.x & 31;
    const int node = blockIdx.x * 8 + warp;
    const int f  = lane << 2;                       // 4 features per lane
    const int hh = (H == 4) ? (lane >> 3) : 0;

    const float ald_d = g_ald[node * H + hh];

    // self loop
    float x = g_als[node * H + hh] + ald_d;
    float l = x > 0.f ? x : 0.2f * x;
    float ex = expf(l);
    float den = ex;
    float4 hv = *(const float4*)&g_h[node * HID + f];
    float4 acc = make_float4(ex * hv.x, ex * hv.y, ex * hv.z, ex * hv.w);

    const int r1 = g_rowp[node + 1];
    for (int k = g_rowp[node]; k < r1; k++) {
        int s = g_csrc[k];
        float xx = g_als[s * H + hh] + ald_d;
        float ll = xx > 0.f ? xx : 0.2f * xx;
        float e2 = expf(ll);
        den += e2;
        float4 h2 = *(const float4*)&g_h[s * HID + f];
        acc.x += e2 * h2.x; acc.y += e2 * h2.y;
        acc.z += e2 * h2.z; acc.w += e2 * h2.w;
    }
    float inv = 1.f / (den + 1e-16f);
    acc.x *= inv; acc.y *= inv; acc.z *= inv; acc.w *= inv;
    *(float4*)&g_out[node * HID + f] = acc;
}

// ======================= BatchNorm stats (partials, no atomics) ==============
__global__ void bn_stats()
{
    int f  = threadIdx.x;              // 128 threads, one per feature
    int n0 = blockIdx.x * BN_CHUNK;
    float s = 0.f, q = 0.f;
    for (int i = 0; i < BN_CHUNK; i++) {
        float v = g_out[(n0 + i) * HID + f];
        s += v; q += v * v;
    }
    g_bnpart[blockIdx.x * (2 * HID) + f]       = s;
    g_bnpart[blockIdx.x * (2 * HID) + HID + f] = q;
}

// 4 blocks x 1024 threads: one warp per feature, strided loads + warp reduce.
__global__ void bn_reduce()
{
    int warp = (blockIdx.x * 32) + (threadIdx.x >> 5);  // feature 0..127
    int lane = threadIdx.x & 31;
    float s = 0.f, q = 0.f;
    for (int b = lane; b < BN_BLOCKS; b += 32) {
        s += g_bnpart[b * (2 * HID) + warp];
        q += g_bnpart[b * (2 * HID) + HID + warp];
    }
#pragma unroll
    for (int o = 16; o; o >>= 1) {
        s += __shfl_down_sync(0xFFFFFFFFu, s, o);
        q += __shfl_down_sync(0xFFFFFFFFu, q, o);
    }
    if (lane == 0) { g_bnsum[warp] = s; g_bnsq[warp] = q; }
}

// ======================= Pool (BN+ReLU fused) + MLP head =====================
__device__ __forceinline__ int lowb(const int* b, int v) {
    int lo = 0, hi = N;
    while (lo < hi) { int m = (lo + hi) >> 1; if (b[m] < v) lo = m + 1; else hi = m; }
    return lo;
}

__global__ void pool_mlp(const int* __restrict__ batch,
                         const float* __restrict__ gma, const float* __restrict__ bta,
                         const float* __restrict__ fw1, const float* __restrict__ fb1,
                         const float* __restrict__ fw2, const float* __restrict__ fb2,
                         float* __restrict__ out)
{
    __shared__ float ph[HID];
    __shared__ int srange[2];
    __shared__ float part[2];
    const int g = blockIdx.x, f = threadIdx.x;   // 128 threads

    if (f == 0) srange[0] = lowb(batch, g);
    if (f == 1) srange[1] = lowb(batch, g + 1);
    __syncthreads();
    const int s0 = srange[0], s1 = srange[1];

    float m   = g_bnsum[f] * (1.0f / N);
    float var = g_bnsq[f] * (1.0f / N) - m * m;
    float rs  = rsqrtf(var + 1e-5f) * gma[f];
    float bt  = bta[f];

    float sum = 0.f;
    for (int n = s0; n < s1; n++) {
        float y = (g_out[n * HID + f] - m) * rs + bt;
        sum += y > 0.f ? y : 0.f;
    }
    float cnt = (float)(s1 - s0);
    ph[f] = sum / (cnt < 1.f ? 1.f : cnt);
    __syncthreads();

    if (f < 64) {
        float acc = fb1[f];
#pragma unroll
        for (int k = 0; k < HID; k++) acc += ph[k] * fw1[k * 64 + f];
        float z = acc > 0.f ? acc : 0.f;
        float p = z * fw2[f];
#pragma unroll
        for (int o = 16; o; o >>= 1) p += __shfl_down_sync(0xFFFFFFFFu, p, o);
        if ((f & 31) == 0) part[f >> 5] = p;
    }
    __syncthreads();
    if (f == 0) out[g] = part[0] + part[1] + fb2[0];
}

// ======================= host driver =========================================
extern "C" void kernel_launch(void* const* d_in, const int* in_sizes, int n_in,
                              void* d_out, int out_size)
{
    const float* x     = (const float*)d_in[0];
    const int*   ei    = (const int*)  d_in[1];
    const int*   batch = (const int*)  d_in[2];
    const float* W1  = (const float*)d_in[3];
    const float* as1 = (const float*)d_in[4];
    const float* ad1 = (const float*)d_in[5];
    const float* g1  = (const float*)d_in[7];
    const float* be1 = (const float*)d_in[8];
    const float* W2  = (const float*)d_in[9];
    const float* as2 = (const float*)d_in[10];
    const float* ad2 = (const float*)d_in[11];
    const float* g2  = (const float*)d_in[13];
    const float* be2 = (const float*)d_in[14];
    const float* W3  = (const float*)d_in[15];
    const float* as3 = (const float*)d_in[16];
    const float* ad3 = (const float*)d_in[17];
    const float* g3  = (const float*)d_in[19];
    const float* be3 = (const float*)d_in[20];
    const float* fw1 = (const float*)d_in[21];
    const float* fb1 = (const float*)d_in[22];
    const float* fw2 = (const float*)d_in[23];
    const float* fb2 = (const float*)d_in[24];
    float* out = (float*)d_out;

    const int CSRE = (E + 255) / 256;
    const int GEMM_GRID = N / 16;     // 6250
    const int AGG_GRID  = N / 8;      // 12500 (8 warps/block)

    // ---- Build CSR (dst-sorted adjacency), reused by all 3 layers
    csr_zero<<<NBLK, 256>>>();
    csr_deg<<<CSRE, 256>>>(ei);
    csr_bsum<<<NBLK, 256>>>();
    csr_scan1<<<1, 512>>>();
    csr_rowp2<<<NBLK, 256>>>();
    csr_fill<<<CSRE, 256>>>(ei);

    // ---- Layer 1: 22 -> 4x32 (input: x)
    gemm_att<FIN, 4, 0><<<GEMM_GRID, 128>>>(x, W1, as1, ad1, nullptr, nullptr);
    node_aggr<4><<<AGG_GRID, 256>>>();
    bn_stats<<<BN_BLOCKS, 128>>>();
    bn_reduce<<<4, 1024>>>();

    // ---- Layer 2: 128 -> 4x32 (input: BN+ReLU(g_out) fused into staging)
    gemm_att<HID, 4, 1><<<GEMM_GRID, 128>>>(nullptr, W2, as2, ad2, g1, be1);
    node_aggr<4><<<AGG_GRID, 256>>>();
    bn_stats<<<BN_BLOCKS, 128>>>();
    bn_reduce<<<4, 1024>>>();

    // ---- Layer 3: 128 -> 1x128
    gemm_att<HID, 1, 1><<<GEMM_GRID, 128>>>(nullptr, W3, as3, ad3, g2, be2);
    node_aggr<1><<<AGG_GRID, 256>>>();
    bn_stats<<<BN_BLOCKS, 128>>>();
    bn_reduce<<<4, 1024>>>();

    // ---- Pool (BN3+ReLU fused) + MLP head
    pool_mlp<<<NG, 128>>>(batch, g3, be3, fw1, fb1, fw2, fb2, out);
}

// round 15
// speedup vs baseline: 1.0627x; 1.0627x over previous
#include <cuda_runtime.h>
#include <cuda_bf16.h>

// Problem constants (fixed by the reference setup)
constexpr int N    = 100000;   // nodes
constexpr int E    = 300000;   // directed edges
constexpr int NG   = 4096;     // graphs
constexpr int HID  = 128;
constexpr int FIN  = 22;

constexpr int NBLK = (N + 255) / 256;    // 391 scan blocks
constexpr int AGG_BLOCKS = N / 8;        // 12500 (8 nodes per aggr block)
constexpr int BNR1 = 50;                 // level-1 reduce blocks
constexpr int BNR_ROWS = AGG_BLOCKS / BNR1;  // 250 rows per level-1 block

// ---------------- scratch (device globals; no allocations allowed) ----------
__device__ float g_h[N * HID];        // transformed features h = A@W (per layer)
__device__ float g_out[N * HID];      // aggregated messages (per layer)
__device__ float g_als[N * 4];        // per-node src attention logits
__device__ float g_ald[N * 4];        // per-node dst attention logits
__device__ float g_bnsum[HID];
__device__ float g_bnsq[HID];
__device__ float g_bnpart[AGG_BLOCKS * 2 * HID];  // per-aggr-block [sum128|sq128]
__device__ float g_bnp2[BNR1 * 2 * HID];
// CSR (built once per launch, reused by all 3 layers)
__device__ int g_deg[N];
__device__ int g_fill[N];
__device__ int g_bsum[NBLK];
__device__ int g_bbase[NBLK];
__device__ int g_rowp[N + 1];
__device__ int g_csrc[E];

// ======================= CSR construction (fully parallel scan) ==============
__global__ void csr_zero() {
    int i = blockIdx.x * 256 + threadIdx.x;
    if (i < N) { g_deg[i] = 0; g_fill[i] = 0; }
}

__global__ void csr_deg(const int* __restrict__ ei) {
    int e = blockIdx.x * 256 + threadIdx.x;
    if (e < E) atomicAdd(&g_deg[ei[E + e]], 1);
}

// Level 1: per-block sum of 256 degrees -> g_bsum
__global__ void csr_bsum() {
    __shared__ int sw[8];
    int b = blockIdx.x, t = threadIdx.x;
    int i = b * 256 + t;
    int v = (i < N) ? g_deg[i] : 0;
#pragma unroll
    for (int o = 16; o; o >>= 1) v += __shfl_down_sync(0xFFFFFFFFu, v, o);
    if ((t & 31) == 0) sw[t >> 5] = v;
    __syncthreads();
    if (t == 0) {
        int s = 0;
#pragma unroll
        for (int j = 0; j < 8; j++) s += sw[j];
        g_bsum[b] = s;
    }
}

// Level 2: single-block exclusive scan of NBLK block sums -> g_bbase
__global__ void csr_scan1() {
    __shared__ int ss[512];
    int t = threadIdx.x;
    int s0 = (t < NBLK) ? g_bsum[t] : 0;
    ss[t] = s0;
    __syncthreads();
    for (int o = 1; o < 512; o <<= 1) {
        int v = (t >= o) ? ss[t - o] : 0;
        __syncthreads();
        ss[t] += v;
        __syncthreads();
    }
    if (t < NBLK) g_bbase[t] = ss[t] - s0;
}

// Level 3: per-block inclusive scan (shfl) + base -> g_rowp
__global__ void csr_rowp2() {
    __shared__ int sw[8];
    int b = blockIdx.x, t = threadIdx.x;
    int lane = t & 31, w = t >> 5;
    int i = b * 256 + t;
    int d = (i < N) ? g_deg[i] : 0;
    int v = d;
#pragma unroll
    for (int o = 1; o < 32; o <<= 1) {
        int u = __shfl_up_sync(0xFFFFFFFFu, v, o);
        if (lane >= o) v += u;
    }
    if (lane == 31) sw[w] = v;
    __syncthreads();
    if (t == 0) {
        int r = 0;
#pragma unroll
        for (int j = 0; j < 8; j++) { int x = sw[j]; sw[j] = r; r += x; }
    }
    __syncthreads();
    int base = g_bbase[b] + sw[w];
    if (i < N)      g_rowp[i] = base + v - d;   // exclusive
    if (i == N - 1) g_rowp[N] = base + v;
}

__global__ void csr_fill(const int* __restrict__ ei) {
    int e = blockIdx.x * 256 + threadIdx.x;
    if (e >= E) return;
    int d = ei[E + e];
    int pos = g_rowp[d] + atomicAdd(&g_fill[d], 1);
    g_csrc[pos] = ei[e];
}

// ======================= GEMM + fused attention projections ==================
// h = A[N,K] @ W[K,128];  al_s[n,h] = sum_c h[n,h*C+c]*a_s[h,c]  (same a_d)
// 128 threads: thread = (fg = t&31 feature group of 4, ng = t>>5 node group
// of 8). NPB=32 nodes/block. A staged in smem as PRE-DUPLICATED f32x2 pairs
// {a,a} so the inner loop needs zero duplication movs; W read as ulonglong2
// (LDG.128) giving {w0,w1},{w2,w3} f32x2 operands directly (features adjacent).
// Per k per warp: 16 FFMA2 + 4 LDS.128 + 1 LDG -> ~70% FFMA2 issue efficiency.
// Attention projections reduce fully intra-warp (8-lane segments per head).
// SRC: 0 = external pointer (layer-1 x); 1 = g_out with fused BN+ReLU.
// Device symbols referenced IN-KERNEL only (host-side symbol pass = ATS host
// shadow = zeros on GB300).
template<int K, int H, int SRC>
__global__ void gemm_att(const float* __restrict__ Aext, const float* __restrict__ W,
                         const float* __restrict__ a_s, const float* __restrict__ a_d,
                         const float* __restrict__ gma, const float* __restrict__ bta)
{
    constexpr int NPB   = 32;
    constexpr int PITCH = NPB + 2;           // 34 * 8B = 272B rows (16B aligned)
    __shared__ __align__(16) unsigned long long sA[K * PITCH];

    const int n0  = blockIdx.x * NPB;
    const int tid = threadIdx.x;

    // Stage NPB rows, k-major, duplicated pairs; BN+ReLU fused when SRC==1.
    for (int i = tid; i < NPB * K; i += 128) {
        int t = i / K, k = i - t * K;
        float v;
        if (SRC == 0) {
            v = Aext[(n0 + t) * K + k];
        } else {
            float raw = g_out[(n0 + t) * K + k];
            float m   = g_bnsum[k] * (1.0f / N);
            float var = g_bnsq[k] * (1.0f / N) - m * m;
            float y = (raw - m) * rsqrtf(var + 1e-5f) * gma[k] + bta[k];
            v = y > 0.f ? y : 0.f;
        }
        unsigned long long vv;
        asm("mov.b64 %0, {%1, %1};" : "=l"(vv) : "r"(__float_as_uint(v)));
        sA[k * PITCH + t] = vv;
    }
    __syncthreads();

    const int fg = tid & 31;   // features fg*4 .. fg*4+3
    const int ng = tid >> 5;   // nodes ng*8 .. ng*8+7  (== warp id)

    unsigned long long acc0[8], acc1[8];
#pragma unroll
    for (int m = 0; m < 8; m++) { acc0[m] = 0ull; acc1[m] = 0ull; }

    const float* Wp = W + fg * 4;
#pragma unroll 2
    for (int k = 0; k < K; k++) {
        // w2.x = {W[k,4fg],W[k,4fg+1]}  w2.y = {W[k,4fg+2],W[k,4fg+3]}
        ulonglong2 w2 = __ldg(reinterpret_cast<const ulonglong2*>(Wp + (size_t)k * HID));
        const ulonglong2* ap =
            reinterpret_cast<const ulonglong2*>(&sA[k * PITCH + ng * 8]);
#pragma unroll
        for (int q = 0; q < 4; q++) {
            ulonglong2 a2 = ap[q];   // dup pairs for nodes 2q, 2q+1 (broadcast)
            asm("fma.rn.f32x2 %0, %1, %2, %0;" : "+l"(acc0[2*q])   : "l"(a2.x), "l"(w2.x));
            asm("fma.rn.f32x2 %0, %1, %2, %0;" : "+l"(acc1[2*q])   : "l"(a2.x), "l"(w2.y));
            asm("fma.rn.f32x2 %0, %1, %2, %0;" : "+l"(acc0[2*q+1]) : "l"(a2.y), "l"(w2.x));
            asm("fma.rn.f32x2 %0, %1, %2, %0;" : "+l"(acc1[2*q+1]) : "l"(a2.y), "l"(w2.y));
        }
    }

    const float as0 = a_s[fg*4], as1 = a_s[fg*4+1], as2 = a_s[fg*4+2], as3 = a_s[fg*4+3];
    const float ad0 = a_d[fg*4], ad1 = a_d[fg*4+1], ad2 = a_d[fg*4+2], ad3 = a_d[fg*4+3];

#pragma unroll
    for (int m = 0; m < 8; m++) {
        unsigned int u0, u1, u2, u3;
        asm("mov.b64 {%0, %1}, %2;" : "=r"(u0), "=r"(u1) : "l"(acc0[m]));
        asm("mov.b64 {%0, %1}, %2;" : "=r"(u2), "=r"(u3) : "l"(acc1[m]));
        float x0 = __uint_as_float(u0), x1 = __uint_as_float(u1);
        float x2 = __uint_as_float(u2), x3 = __uint_as_float(u3);
        const int node = n0 + ng * 8 + m;
        *(float4*)&g_h[node * HID + fg * 4] = make_float4(x0, x1, x2, x3);

        float vs = x0*as0 + x1*as1 + x2*as2 + x3*as3;
        float vd = x0*ad0 + x1*ad1 + x2*ad2 + x3*ad3;
        if (H == 4) {
            // reduce within 8-lane segment (one head each)
#pragma unroll
            for (int o = 4; o; o >>= 1) {
                vs += __shfl_down_sync(0xFFFFFFFFu, vs, o, 8);
                vd += __shfl_down_sync(0xFFFFFFFFu, vd, o, 8);
            }
            if ((fg & 7) == 0) {
                g_als[node * 4 + (fg >> 3)] = vs;
                g_ald[node * 4 + (fg >> 3)] = vd;
            }
        } else {
#pragma unroll
            for (int o = 16; o; o >>= 1) {
                vs += __shfl_down_sync(0xFFFFFFFFu, vs, o);
                vd += __shfl_down_sync(0xFFFFFFFFu, vd, o);
            }
            if (fg == 0) { g_als[node] = vs; g_ald[node] = vd; }
        }
    }
}

// ======================= Fused attention softmax + aggregation + BN partials =
// One warp per dst node: out[d] = (sum_e ex_e * h[src_e]) / (sum_e ex_e + 1e-16)
// with ex_e = exp(leaky_relu(als[src]+ald[d])). Segment_max skipped
// (shift-invariant; logits O(1)). BN partial sums/squares for the block's 8
// nodes are reduced in smem and written to g_bnpart (no re-read of g_out).
template<int H>
__global__ void node_aggr()
{
    __shared__ float sp[8][2 * HID];   // per-warp [sum128 | sq128]
    const int warp = threadIdx.x >> 5, lane = threadIdx.x & 31;
    const int node = blockIdx.x * 8 + warp;
    const int f  = lane << 2;                       // 4 features per lane
    const int hh = (H == 4) ? (lane >> 3) : 0;

    const float ald_d = g_ald[node * H + hh];

    // self loop
    float x = g_als[node * H + hh] + ald_d;
    float l = x > 0.f ? x : 0.2f * x;
    float ex = expf(l);
    float den = ex;
    float4 hv = *(const float4*)&g_h[node * HID + f];
    float4 acc = make_float4(ex * hv.x, ex * hv.y, ex * hv.z, ex * hv.w);

    const int r1 = g_rowp[node + 1];
    for (int k = g_rowp[node]; k < r1; k++) {
        int s = g_csrc[k];
        float xx = g_als[s * H + hh] + ald_d;
        float ll = xx > 0.f ? xx : 0.2f * xx;
        float e2 = expf(ll);
        den += e2;
        float4 h2 = *(const float4*)&g_h[s * HID + f];
        acc.x += e2 * h2.x; acc.y += e2 * h2.y;
        acc.z += e2 * h2.z; acc.w += e2 * h2.w;
    }
    float inv = 1.f / (den + 1e-16f);
    acc.x *= inv; acc.y *= inv; acc.z *= inv; acc.w *= inv;
    *(float4*)&g_out[node * HID + f] = acc;

    // BN partials: per-warp stores (conflict-free), then cross-warp reduce.
    *(float4*)&sp[warp][f] = acc;
    *(float4*)&sp[warp][HID + f] = make_float4(acc.x*acc.x, acc.y*acc.y,
                                               acc.z*acc.z, acc.w*acc.w);
    __syncthreads();
    if (threadIdx.x < 2 * HID) {
        float s = 0.f;
#pragma unroll
        for (int w = 0; w < 8; w++) s += sp[w][threadIdx.x];
        g_bnpart[blockIdx.x * (2 * HID) + threadIdx.x] = s;
    }
}

// ======================= BN partial reduction (two tiny levels) ==============
__global__ void bn_reduce1() {
    int b = blockIdx.x, t = threadIdx.x;   // 50 blocks x 256
    float s = 0.f;
    const float* p = &g_bnpart[b * BNR_ROWS * (2 * HID) + t];
#pragma unroll 5
    for (int r = 0; r < BNR_ROWS; r++) s += p[r * (2 * HID)];
    g_bnp2[b * (2 * HID) + t] = s;
}

__global__ void bn_reduce2() {
    int t = threadIdx.x;                   // 1 block x 256
    float s = 0.f;
#pragma unroll
    for (int r = 0; r < BNR1; r++) s += g_bnp2[r * (2 * HID) + t];
    if (t < HID) g_bnsum[t] = s;
    else         g_bnsq[t - HID] = s;
}

// ======================= Pool (BN+ReLU fused) + MLP head =====================
__device__ __forceinline__ int lowb(const int* b, int v) {
    int lo = 0, hi = N;
    while (lo < hi) { int m = (lo + hi) >> 1; if (b[m] < v) lo = m + 1; else hi = m; }
    return lo;
}

__global__ void pool_mlp(const int* __restrict__ batch,
                         const float* __restrict__ gma, const float* __restrict__ bta,
                         const float* __restrict__ fw1, const float* __restrict__ fb1,
                         const float* __restrict__ fw2, const float* __restrict__ fb2,
                         float* __restrict__ out)
{
    __shared__ float ph[HID];
    __shared__ int srange[2];
    __shared__ float part[2];
    const int g = blockIdx.x, f = threadIdx.x;   // 128 threads

    if (f == 0) srange[0] = lowb(batch, g);
    if (f == 1) srange[1] = lowb(batch, g + 1);
    __syncthreads();
    const int s0 = srange[0], s1 = srange[1];

    float m   = g_bnsum[f] * (1.0f / N);
    float var = g_bnsq[f] * (1.0f / N) - m * m;
    float rs  = rsqrtf(var + 1e-5f) * gma[f];
    float bt  = bta[f];

    float sum = 0.f;
    for (int n = s0; n < s1; n++) {
        float y = (g_out[n * HID + f] - m) * rs + bt;
        sum += y > 0.f ? y : 0.f;
    }
    float cnt = (float)(s1 - s0);
    ph[f] = sum / (cnt < 1.f ? 1.f : cnt);
    __syncthreads();

    if (f < 64) {
        float acc = fb1[f];
#pragma unroll
        for (int k = 0; k < HID; k++) acc += ph[k] * fw1[k * 64 + f];
        float z = acc > 0.f ? acc : 0.f;
        float p = z * fw2[f];
#pragma unroll
        for (int o = 16; o; o >>= 1) p += __shfl_down_sync(0xFFFFFFFFu, p, o);
        if ((f & 31) == 0) part[f >> 5] = p;
    }
    __syncthreads();
    if (f == 0) out[g] = part[0] + part[1] + fb2[0];
}

// ======================= host driver =========================================
extern "C" void kernel_launch(void* const* d_in, const int* in_sizes, int n_in,
                              void* d_out, int out_size)
{
    const float* x     = (const float*)d_in[0];
    const int*   ei    = (const int*)  d_in[1];
    const int*   batch = (const int*)  d_in[2];
    const float* W1  = (const float*)d_in[3];
    const float* as1 = (const float*)d_in[4];
    const float* ad1 = (const float*)d_in[5];
    const float* g1  = (const float*)d_in[7];
    const float* be1 = (const float*)d_in[8];
    const float* W2  = (const float*)d_in[9];
    const float* as2 = (const float*)d_in[10];
    const float* ad2 = (const float*)d_in[11];
    const float* g2  = (const float*)d_in[13];
    const float* be2 = (const float*)d_in[14];
    const float* W3  = (const float*)d_in[15];
    const float* as3 = (const float*)d_in[16];
    const float* ad3 = (const float*)d_in[17];
    const float* g3  = (const float*)d_in[19];
    const float* be3 = (const float*)d_in[20];
    const float* fw1 = (const float*)d_in[21];
    const float* fb1 = (const float*)d_in[22];
    const float* fw2 = (const float*)d_in[23];
    const float* fb2 = (const float*)d_in[24];
    float* out = (float*)d_out;

    const int CSRE = (E + 255) / 256;
    const int GEMM_GRID = N / 32;     // 3125

    // ---- Build CSR (dst-sorted adjacency), reused by all 3 layers
    csr_zero<<<NBLK, 256>>>();
    csr_deg<<<CSRE, 256>>>(ei);
    csr_bsum<<<NBLK, 256>>>();
    csr_scan1<<<1, 512>>>();
    csr_rowp2<<<NBLK, 256>>>();
    csr_fill<<<CSRE, 256>>>(ei);

    // ---- Layer 1: 22 -> 4x32 (input: x)
    gemm_att<FIN, 4, 0><<<GEMM_GRID, 128>>>(x, W1, as1, ad1, nullptr, nullptr);
    node_aggr<4><<<AGG_BLOCKS, 256>>>();
    bn_reduce1<<<BNR1, 256>>>();
    bn_reduce2<<<1, 256>>>();

    // ---- Layer 2: 128 -> 4x32 (input: BN+ReLU(g_out) fused into staging)
    gemm_att<HID, 4, 1><<<GEMM_GRID, 128>>>(nullptr, W2, as2, ad2, g1, be1);
    node_aggr<4><<<AGG_BLOCKS, 256>>>();
    bn_reduce1<<<BNR1, 256>>>();
    bn_reduce2<<<1, 256>>>();

    // ---- Layer 3: 128 -> 1x128
    gemm_att<HID, 1, 1><<<GEMM_GRID, 128>>>(nullptr, W3, as3, ad3, g2, be2);
    node_aggr<1><<<AGG_BLOCKS, 256>>>();
    bn_reduce1<<<BNR1, 256>>>();
    bn_reduce2<<<1, 256>>>();

    // ---- Pool (BN3+ReLU fused) + MLP head
    pool_mlp<<<NG, 128>>>(batch, g3, be3, fw1, fb1, fw2, fb2, out);
}

// round 16
// speedup vs baseline: 1.1052x; 1.0400x over previous
#include <cuda_runtime.h>
#include <cuda_bf16.h>

// Problem constants (fixed by the reference setup)
constexpr int N    = 100000;   // nodes
constexpr int E    = 300000;   // directed edges
constexpr int NG   = 4096;     // graphs
constexpr int HID  = 128;
constexpr int FIN  = 22;

constexpr int NBLK = (N + 255) / 256;    // 391 scan blocks
constexpr int AGG_BLOCKS = N / 32;       // 3125 (32 nodes per aggr block)
constexpr int BNR1 = 25;                 // level-1 reduce blocks
constexpr int BNR_ROWS = AGG_BLOCKS / BNR1;  // 125 rows per level-1 block

// ---------------- scratch (device globals; no allocations allowed) ----------
__device__ float g_h[N * HID];        // transformed features h = A@W (per layer)
__device__ float g_out[N * HID];      // aggregated messages (per layer)
__device__ float g_als[N * 4];        // per-node src attention logits
__device__ float g_ald[N * 4];        // per-node dst attention logits
__device__ float g_bnsum[HID];
__device__ float g_bnsq[HID];
__device__ float g_bnpart[AGG_BLOCKS * 2 * HID];  // per-aggr-block [sum128|sq128]
__device__ float g_bnp2[BNR1 * 2 * HID];
// CSR (built once per launch, reused by all 3 layers)
__device__ int g_deg[N];
__device__ int g_fill[N];
__device__ int g_bsum[NBLK];
__device__ int g_bbase[NBLK];
__device__ int g_rowp[N + 1];
__device__ int g_csrc[E];

// ======================= CSR construction (fully parallel scan) ==============
__global__ void csr_zero() {
    int i = blockIdx.x * 256 + threadIdx.x;
    if (i < N) { g_deg[i] = 0; g_fill[i] = 0; }
}

__global__ void csr_deg(const int* __restrict__ ei) {
    int e = blockIdx.x * 256 + threadIdx.x;
    if (e < E) atomicAdd(&g_deg[ei[E + e]], 1);
}

// Level 1: per-block sum of 256 degrees -> g_bsum
__global__ void csr_bsum() {
    __shared__ int sw[8];
    int b = blockIdx.x, t = threadIdx.x;
    int i = b * 256 + t;
    int v = (i < N) ? g_deg[i] : 0;
#pragma unroll
    for (int o = 16; o; o >>= 1) v += __shfl_down_sync(0xFFFFFFFFu, v, o);
    if ((t & 31) == 0) sw[t >> 5] = v;
    __syncthreads();
    if (t == 0) {
        int s = 0;
#pragma unroll
        for (int j = 0; j < 8; j++) s += sw[j];
        g_bsum[b] = s;
    }
}

// Level 2: single-block exclusive scan of NBLK block sums -> g_bbase
__global__ void csr_scan1() {
    __shared__ int ss[512];
    int t = threadIdx.x;
    int s0 = (t < NBLK) ? g_bsum[t] : 0;
    ss[t] = s0;
    __syncthreads();
    for (int o = 1; o < 512; o <<= 1) {
        int v = (t >= o) ? ss[t - o] : 0;
        __syncthreads();
        ss[t] += v;
        __syncthreads();
    }
    if (t < NBLK) g_bbase[t] = ss[t] - s0;
}

// Level 3: per-block inclusive scan (shfl) + base -> g_rowp
__global__ void csr_rowp2() {
    __shared__ int sw[8];
    int b = blockIdx.x, t = threadIdx.x;
    int lane = t & 31, w = t >> 5;
    int i = b * 256 + t;
    int d = (i < N) ? g_deg[i] : 0;
    int v = d;
#pragma unroll
    for (int o = 1; o < 32; o <<= 1) {
        int u = __shfl_up_sync(0xFFFFFFFFu, v, o);
        if (lane >= o) v += u;
    }
    if (lane == 31) sw[w] = v;
    __syncthreads();
    if (t == 0) {
        int r = 0;
#pragma unroll
        for (int j = 0; j < 8; j++) { int x = sw[j]; sw[j] = r; r += x; }
    }
    __syncthreads();
    int base = g_bbase[b] + sw[w];
    if (i < N)      g_rowp[i] = base + v - d;   // exclusive
    if (i == N - 1) g_rowp[N] = base + v;
}

__global__ void csr_fill(const int* __restrict__ ei) {
    int e = blockIdx.x * 256 + threadIdx.x;
    if (e >= E) return;
    int d = ei[E + e];
    int pos = g_rowp[d] + atomicAdd(&g_fill[d], 1);
    g_csrc[pos] = ei[e];
}

// ======================= GEMM + fused attention projections ==================
// h = A[N,K] @ W[K,128];  al_s[n,h] = sum_c h[n,h*C+c]*a_s[h,c]  (same a_d)
// 128 threads: thread = (fg = t&31 feature group of 4, ng = t>>5 node group
// of 8). NPB=32 nodes/block. A staged in smem as PRE-DUPLICATED f32x2 pairs;
// W read as ulonglong2 (LDG.128) giving {w0,w1},{w2,w3} f32x2 operands
// directly. SRC: 0 = external pointer (layer-1 x); 1 = g_out with fused
// BN+ReLU. Device symbols referenced IN-KERNEL only (host-side symbol pass =
// ATS host shadow = zeros on GB300).
template<int K, int H, int SRC>
__global__ void gemm_att(const float* __restrict__ Aext, const float* __restrict__ W,
                         const float* __restrict__ a_s, const float* __restrict__ a_d,
                         const float* __restrict__ gma, const float* __restrict__ bta)
{
    constexpr int NPB   = 32;
    constexpr int PITCH = NPB + 2;           // 34 * 8B rows (16B aligned)
    __shared__ __align__(16) unsigned long long sA[K * PITCH];

    const int n0  = blockIdx.x * NPB;
    const int tid = threadIdx.x;

    // Stage NPB rows, k-major, duplicated pairs; BN+ReLU fused when SRC==1.
    for (int i = tid; i < NPB * K; i += 128) {
        int t = i / K, k = i - t * K;
        float v;
        if (SRC == 0) {
            v = Aext[(n0 + t) * K + k];
        } else {
            float raw = g_out[(n0 + t) * K + k];
            float m   = g_bnsum[k] * (1.0f / N);
            float var = g_bnsq[k] * (1.0f / N) - m * m;
            float y = (raw - m) * rsqrtf(var + 1e-5f) * gma[k] + bta[k];
            v = y > 0.f ? y : 0.f;
        }
        unsigned long long vv;
        asm("mov.b64 %0, {%1, %1};" : "=l"(vv) : "r"(__float_as_uint(v)));
        sA[k * PITCH + t] = vv;
    }
    __syncthreads();

    const int fg = tid & 31;   // features fg*4 .. fg*4+3
    const int ng = tid >> 5;   // nodes ng*8 .. ng*8+7  (== warp id)

    unsigned long long acc0[8], acc1[8];
#pragma unroll
    for (int m = 0; m < 8; m++) { acc0[m] = 0ull; acc1[m] = 0ull; }

    const float* Wp = W + fg * 4;
#pragma unroll 2
    for (int k = 0; k < K; k++) {
        ulonglong2 w2 = __ldg(reinterpret_cast<const ulonglong2*>(Wp + (size_t)k * HID));
        const ulonglong2* ap =
            reinterpret_cast<const ulonglong2*>(&sA[k * PITCH + ng * 8]);
#pragma unroll
        for (int q = 0; q < 4; q++) {
            ulonglong2 a2 = ap[q];   // dup pairs for nodes 2q, 2q+1 (broadcast)
            asm("fma.rn.f32x2 %0, %1, %2, %0;" : "+l"(acc0[2*q])   : "l"(a2.x), "l"(w2.x));
            asm("fma.rn.f32x2 %0, %1, %2, %0;" : "+l"(acc1[2*q])   : "l"(a2.x), "l"(w2.y));
            asm("fma.rn.f32x2 %0, %1, %2, %0;" : "+l"(acc0[2*q+1]) : "l"(a2.y), "l"(w2.x));
            asm("fma.rn.f32x2 %0, %1, %2, %0;" : "+l"(acc1[2*q+1]) : "l"(a2.y), "l"(w2.y));
        }
    }

    const float as0 = a_s[fg*4], as1 = a_s[fg*4+1], as2 = a_s[fg*4+2], as3 = a_s[fg*4+3];
    const float ad0 = a_d[fg*4], ad1 = a_d[fg*4+1], ad2 = a_d[fg*4+2], ad3 = a_d[fg*4+3];

#pragma unroll
    for (int m = 0; m < 8; m++) {
        unsigned int u0, u1, u2, u3;
        asm("mov.b64 {%0, %1}, %2;" : "=r"(u0), "=r"(u1) : "l"(acc0[m]));
        asm("mov.b64 {%0, %1}, %2;" : "=r"(u2), "=r"(u3) : "l"(acc1[m]));
        float x0 = __uint_as_float(u0), x1 = __uint_as_float(u1);
        float x2 = __uint_as_float(u2), x3 = __uint_as_float(u3);
        const int node = n0 + ng * 8 + m;
        *(float4*)&g_h[node * HID + fg * 4] = make_float4(x0, x1, x2, x3);

        float vs = x0*as0 + x1*as1 + x2*as2 + x3*as3;
        float vd = x0*ad0 + x1*ad1 + x2*ad2 + x3*ad3;
        if (H == 4) {
#pragma unroll
            for (int o = 4; o; o >>= 1) {
                vs += __shfl_down_sync(0xFFFFFFFFu, vs, o, 8);
                vd += __shfl_down_sync(0xFFFFFFFFu, vd, o, 8);
            }
            if ((fg & 7) == 0) {
                g_als[node * 4 + (fg >> 3)] = vs;
                g_ald[node * 4 + (fg >> 3)] = vd;
            }
        } else {
#pragma unroll
            for (int o = 16; o; o >>= 1) {
                vs += __shfl_down_sync(0xFFFFFFFFu, vs, o);
                vd += __shfl_down_sync(0xFFFFFFFFu, vd, o);
            }
            if (fg == 0) { g_als[node] = vs; g_ald[node] = vd; }
        }
    }
}

// ======================= Fused attention softmax + aggregation + BN partials =
// 8-lane node groups: warp = 4 nodes, lane handles 16 features (4x float4).
// Per warp iteration, 4 edges progress simultaneously (csrc/als/exp amortized
// 4x vs one-warp-per-node). out[d] = sum_e ex_e*h[src_e] / (sum_e ex_e+1e-16),
// ex_e = __expf(leaky(als[src]+ald[d])). Segment_max skipped (shift-invariant;
// logits O(1)). BN partials: butterfly-shfl across the 4 node groups, then
// per-block smem reduce -> g_bnpart.
template<int H>
__global__ void node_aggr()
{
    __shared__ float sp[8][2 * HID];   // per-warp [sum128 | sq128]
    const int warp = threadIdx.x >> 5, lane = threadIdx.x & 31;
    const int grp  = lane >> 3;        // node group 0..3
    const int ln8  = lane & 7;         // lane within group
    const int node = blockIdx.x * 32 + warp * 4 + grp;
    const int f0 = ln8 * 16;           // 16 contiguous features per lane
    const int hh = (H == 4) ? (ln8 >> 1) : 0;  // features f0..f0+15 in one head

    const float ald_d = g_ald[node * H + hh];

    // self loop
    float x = g_als[node * H + hh] + ald_d;
    float l = x > 0.f ? x : 0.2f * x;
    float ex = __expf(l);
    float den = ex;
    const float4* hp = (const float4*)&g_h[node * HID + f0];
    float4 a0 = hp[0], a1 = hp[1], a2 = hp[2], a3 = hp[3];
    a0.x*=ex; a0.y*=ex; a0.z*=ex; a0.w*=ex;
    a1.x*=ex; a1.y*=ex; a1.z*=ex; a1.w*=ex;
    a2.x*=ex; a2.y*=ex; a2.z*=ex; a2.w*=ex;
    a3.x*=ex; a3.y*=ex; a3.z*=ex; a3.w*=ex;

    const int r1 = g_rowp[node + 1];
    for (int k = g_rowp[node]; k < r1; k++) {
        int s = g_csrc[k];
        float xx = g_als[s * H + hh] + ald_d;
        float ll = xx > 0.f ? xx : 0.2f * xx;
        float e2 = __expf(ll);
        den += e2;
        const float4* sph = (const float4*)&g_h[s * HID + f0];
        float4 h0 = sph[0], h1 = sph[1], h2 = sph[2], h3 = sph[3];
        a0.x += e2*h0.x; a0.y += e2*h0.y; a0.z += e2*h0.z; a0.w += e2*h0.w;
        a1.x += e2*h1.x; a1.y += e2*h1.y; a1.z += e2*h1.z; a1.w += e2*h1.w;
        a2.x += e2*h2.x; a2.y += e2*h2.y; a2.z += e2*h2.z; a2.w += e2*h2.w;
        a3.x += e2*h3.x; a3.y += e2*h3.y; a3.z += e2*h3.z; a3.w += e2*h3.w;
    }
    float inv = 1.f / (den + 1e-16f);
    a0.x*=inv; a0.y*=inv; a0.z*=inv; a0.w*=inv;
    a1.x*=inv; a1.y*=inv; a1.z*=inv; a1.w*=inv;
    a2.x*=inv; a2.y*=inv; a2.z*=inv; a2.w*=inv;
    a3.x*=inv; a3.y*=inv; a3.z*=inv; a3.w*=inv;
    float4* op = (float4*)&g_out[node * HID + f0];
    op[0] = a0; op[1] = a1; op[2] = a2; op[3] = a3;

    // BN partials: sums & squares, butterfly over node groups (lane bits 3,4)
    float sv[16] = {a0.x,a0.y,a0.z,a0.w, a1.x,a1.y,a1.z,a1.w,
                    a2.x,a2.y,a2.z,a2.w, a3.x,a3.y,a3.z,a3.w};
    float qv[16];
#pragma unroll
    for (int i = 0; i < 16; i++) qv[i] = sv[i] * sv[i];
#pragma unroll
    for (int i = 0; i < 16; i++) {
        sv[i] += __shfl_xor_sync(0xFFFFFFFFu, sv[i], 8);
        sv[i] += __shfl_xor_sync(0xFFFFFFFFu, sv[i], 16);
        qv[i] += __shfl_xor_sync(0xFFFFFFFFu, qv[i], 8);
        qv[i] += __shfl_xor_sync(0xFFFFFFFFu, qv[i], 16);
    }
    if (grp == 0) {
#pragma unroll
        for (int i = 0; i < 16; i++) {
            sp[warp][f0 + i]       = sv[i];
            sp[warp][HID + f0 + i] = qv[i];
        }
    }
    __syncthreads();
    if (threadIdx.x < 2 * HID) {
        float s = 0.f;
#pragma unroll
        for (int w = 0; w < 8; w++) s += sp[w][threadIdx.x];
        g_bnpart[blockIdx.x * (2 * HID) + threadIdx.x] = s;
    }
}

// ======================= BN partial reduction (two tiny levels) ==============
__global__ void bn_reduce1() {
    int b = blockIdx.x, t = threadIdx.x;   // 25 blocks x 256
    float s = 0.f;
    const float* p = &g_bnpart[b * BNR_ROWS * (2 * HID) + t];
#pragma unroll 5
    for (int r = 0; r < BNR_ROWS; r++) s += p[r * (2 * HID)];
    g_bnp2[b * (2 * HID) + t] = s;
}

__global__ void bn_reduce2() {
    int t = threadIdx.x;                   // 1 block x 256
    float s = 0.f;
#pragma unroll
    for (int r = 0; r < BNR1; r++) s += g_bnp2[r * (2 * HID) + t];
    if (t < HID) g_bnsum[t] = s;
    else         g_bnsq[t - HID] = s;
}

// ======================= Pool (BN+ReLU fused) + MLP head =====================
__device__ __forceinline__ int lowb(const int* b, int v) {
    int lo = 0, hi = N;
    while (lo < hi) { int m = (lo + hi) >> 1; if (b[m] < v) lo = m + 1; else hi = m; }
    return lo;
}

__global__ void pool_mlp(const int* __restrict__ batch,
                         const float* __restrict__ gma, const float* __restrict__ bta,
                         const float* __restrict__ fw1, const float* __restrict__ fb1,
                         const float* __restrict__ fw2, const float* __restrict__ fb2,
                         float* __restrict__ out)
{
    __shared__ float ph[HID];
    __shared__ int srange[2];
    __shared__ float part[2];
    const int g = blockIdx.x, f = threadIdx.x;   // 128 threads

    if (f == 0) srange[0] = lowb(batch, g);
    if (f == 1) srange[1] = lowb(batch, g + 1);
    __syncthreads();
    const int s0 = srange[0], s1 = srange[1];

    float m   = g_bnsum[f] * (1.0f / N);
    float var = g_bnsq[f] * (1.0f / N) - m * m;
    float rs  = rsqrtf(var + 1e-5f) * gma[f];
    float bt  = bta[f];

    float sum = 0.f;
    for (int n = s0; n < s1; n++) {
        float y = (g_out[n * HID + f] - m) * rs + bt;
        sum += y > 0.f ? y : 0.f;
    }
    float cnt = (float)(s1 - s0);
    ph[f] = sum / (cnt < 1.f ? 1.f : cnt);
    __syncthreads();

    if (f < 64) {
        float acc = fb1[f];
#pragma unroll
        for (int k = 0; k < HID; k++) acc += ph[k] * fw1[k * 64 + f];
        float z = acc > 0.f ? acc : 0.f;
        float p = z * fw2[f];
#pragma unroll
        for (int o = 16; o; o >>= 1) p += __shfl_down_sync(0xFFFFFFFFu, p, o);
        if ((f & 31) == 0) part[f >> 5] = p;
    }
    __syncthreads();
    if (f == 0) out[g] = part[0] + part[1] + fb2[0];
}

// ======================= host driver =========================================
extern "C" void kernel_launch(void* const* d_in, const int* in_sizes, int n_in,
                              void* d_out, int out_size)
{
    const float* x     = (const float*)d_in[0];
    const int*   ei    = (const int*)  d_in[1];
    const int*   batch = (const int*)  d_in[2];
    const float* W1  = (const float*)d_in[3];
    const float* as1 = (const float*)d_in[4];
    const float* ad1 = (const float*)d_in[5];
    const float* g1  = (const float*)d_in[7];
    const float* be1 = (const float*)d_in[8];
    const float* W2  = (const float*)d_in[9];
    const float* as2 = (const float*)d_in[10];
    const float* ad2 = (const float*)d_in[11];
    const float* g2  = (const float*)d_in[13];
    const float* be2 = (const float*)d_in[14];
    const float* W3  = (const float*)d_in[15];
    const float* as3 = (const float*)d_in[16];
    const float* ad3 = (const float*)d_in[17];
    const float* g3  = (const float*)d_in[19];
    const float* be3 = (const float*)d_in[20];
    const float* fw1 = (const float*)d_in[21];
    const float* fb1 = (const float*)d_in[22];
    const float* fw2 = (const float*)d_in[23];
    const float* fb2 = (const float*)d_in[24];
    float* out = (float*)d_out;

    const int CSRE = (E + 255) / 256;
    const int GEMM_GRID = N / 32;     // 3125

    // ---- Build CSR (dst-sorted adjacency), reused by all 3 layers
    csr_zero<<<NBLK, 256>>>();
    csr_deg<<<CSRE, 256>>>(ei);
    csr_bsum<<<NBLK, 256>>>();
    csr_scan1<<<1, 512>>>();
    csr_rowp2<<<NBLK, 256>>>();
    csr_fill<<<CSRE, 256>>>(ei);

    // ---- Layer 1: 22 -> 4x32 (input: x)
    gemm_att<FIN, 4, 0><<<GEMM_GRID, 128>>>(x, W1, as1, ad1, nullptr, nullptr);
    node_aggr<4><<<AGG_BLOCKS, 256>>>();
    bn_reduce1<<<BNR1, 256>>>();
    bn_reduce2<<<1, 256>>>();

    // ---- Layer 2: 128 -> 4x32 (input: BN+ReLU(g_out) fused into staging)
    gemm_att<HID, 4, 1><<<GEMM_GRID, 128>>>(nullptr, W2, as2, ad2, g1, be1);
    node_aggr<4><<<AGG_BLOCKS, 256>>>();
    bn_reduce1<<<BNR1, 256>>>();
    bn_reduce2<<<1, 256>>>();

    // ---- Layer 3: 128 -> 1x128
    gemm_att<HID, 1, 1><<<GEMM_GRID, 128>>>(nullptr, W3, as3, ad3, g2, be2);
    node_aggr<1><<<AGG_BLOCKS, 256>>>();
    bn_reduce1<<<BNR1, 256>>>();
    bn_reduce2<<<1, 256>>>();

    // ---- Pool (BN3+ReLU fused) + MLP head
    pool_mlp<<<NG, 128>>>(batch, g3, be3, fw1, fb1, fw2, fb2, out);
}